// round 17
// baseline (speedup 1.0000x reference)
#include <cuda_runtime.h>
#include <cuda_fp16.h>
#include <cstdint>

#define NPOS 16384   // 128*128 guide positions
#define LPOS 1024    // 32*32 low positions
#define DMODEL 512

// ---------------------------------------------------------------------------
// Scratch (static device globals — no allocation APIs allowed)
// ---------------------------------------------------------------------------
__device__ __half g_Af [NPOS * DMODEL];          // fp16 activations (guide, then msg)
__device__ __half g_Lf [LPOS * DMODEL];          // fp16 low activations
__device__ __half g_Whi[4 * DMODEL * DMODEL];    // weight hi (fp16)
__device__ __half g_Q [NPOS * DMODEL];           // fp16 Q, then fp16 M2
__device__ __half g_K [LPOS * DMODEL];           // fp16 K
__device__ __half g_V [LPOS * DMODEL];           // fp16 V

// ---------------------------------------------------------------------------
// Baseline-PTX helpers (sm_80+ features only: work on plain sm_103 target)
// ---------------------------------------------------------------------------
__device__ __forceinline__ uint32_t smem_u32(const void* p) {
    uint32_t a;
    asm("{ .reg .u64 t; cvta.to.shared.u64 t, %1; cvt.u32.u64 %0, t; }" : "=r"(a) : "l"(p));
    return a;
}

#define CP16(dst, src) \
    asm volatile("cp.async.cg.shared.global [%0], [%1], 16;" :: "r"(dst), "l"(src))
#define CP_COMMIT() asm volatile("cp.async.commit_group;" ::: "memory")
#define CP_WAIT(n)  asm volatile("cp.async.wait_group %0;" :: "n"(n) : "memory")

#define LDSM4(r0, r1, r2, r3, addr) \
    asm volatile("ldmatrix.sync.aligned.m8n8.x4.shared.b16 {%0,%1,%2,%3}, [%4];" \
        : "=r"(r0), "=r"(r1), "=r"(r2), "=r"(r3) : "r"(addr))

#define MMA16816F(d, a, b) \
    asm volatile("mma.sync.aligned.m16n8k16.row.col.f32.f16.f16.f32 " \
        "{%0,%1,%2,%3}, {%4,%5,%6,%7}, {%8,%9}, {%0,%1,%2,%3};" \
        : "+f"((d)[0]), "+f"((d)[1]), "+f"((d)[2]), "+f"((d)[3]) \
        : "r"((a)[0]), "r"((a)[1]), "r"((a)[2]), "r"((a)[3]), \
          "r"((b)[0]), "r"((b)[1]))

// ---------------------------------------------------------------------------
// mma_gemm: C[m][n] = sum_k A[m][k]*B[n][k], K=512, fp16 out.
// A and B rounded to fp16 (1 MMA per k16), fp32 accumulate.
// CTA: 128x128 tile, 128 threads = 4 warps (2m x 2n), warp tile 64x64.
// K chunks of 64, THREE smem stages, one barrier per chunk: each cp.async
// batch has ~2 chunk-compute times to land (CP_WAIT(1) off critical path).
// Pitch 144B (128B data + 16B skew) keeps LDSM conflict-free.
// Three independent GEMMs selected by blockIdx.z; CTAs with
// blockIdx.y >= mtiles exit immediately (QKV share one launch).
// ---------------------------------------------------------------------------
#define PITCH 144
#define TILE_B (128 * PITCH)            // 18432 B per operand tile
#define STAGE_B (2 * TILE_B)            // A, Bhi = 36864 B per stage
#define NSTAGE 3
#define EPI_PITCH 136                   // halves per staged row (272B, 4-bank skew)

struct GemmArgs {
    const __half* A;
    const __half* Bhi;
    __half* C;
    int mtiles;
};

__global__ __launch_bounds__(128, 2)
void mma_gemm(GemmArgs g0, GemmArgs g1, GemmArgs g2)
{
    const GemmArgs& ga_ = (blockIdx.z == 0) ? g0 : (blockIdx.z == 1) ? g1 : g2;
    if ((int)blockIdx.y >= ga_.mtiles) return;

    const __half* __restrict__ A   = ga_.A;
    const __half* __restrict__ Bhi = ga_.Bhi;

    extern __shared__ char smem[];
    const uint32_t sb = smem_u32(smem);

    const int tid  = threadIdx.x;
    const int wid  = tid >> 5;
    const int lane = tid & 31;
    const int bm0  = blockIdx.y * 128;
    const int bn0  = blockIdx.x * 128;
    const int wm   = (wid >> 1) * 64;    // warp m offset in tile
    const int wn   = (wid & 1) * 64;     // warp n offset in tile

    float acc[4][8][4];
#pragma unroll
    for (int i = 0; i < 4; i++)
#pragma unroll
        for (int j = 0; j < 8; j++)
#pragma unroll
            for (int r = 0; r < 4; r++) acc[i][j][r] = 0.f;

    // ---- async stage loader: 16 x 16B per thread per stage (k64 chunk)
    auto load_stage = [&](int s, int k0) {
        const uint32_t base = sb + s * STAGE_B;
#pragma unroll
        for (int i = 0; i < 8; i++) {
            const int idx = tid + 128 * i;        // 0..1023
            const int row = idx >> 3;             // 0..127
            const int c   = idx & 7;              // 16B chunk in 128B row
            const uint32_t off = row * PITCH + c * 16;
            const size_t ga = ((size_t)(bm0 + row) * 512 + k0) * 2 + c * 16;
            const size_t gb = ((size_t)(bn0 + row) * 512 + k0) * 2 + c * 16;
            CP16(base + off,          (const char*)A   + ga);
            CP16(base + TILE_B + off, (const char*)Bhi + gb);
        }
        CP_COMMIT();
    };

    // ---- compute one k64 chunk from stage s (4 k16 steps)
    auto compute_stage = [&](int s) {
        const uint32_t base = sb + s * STAGE_B;
#pragma unroll
        for (int kk = 0; kk < 4; kk++) {
            const uint32_t koff = kk * 32;        // byte offset of k16 step

            uint32_t a[4][4];
#pragma unroll
            for (int f = 0; f < 4; f++) {
                const uint32_t ra = base +
                    (uint32_t)(wm + f * 16 + (lane & 15)) * PITCH +
                    koff + ((lane >> 4) << 4);
                LDSM4(a[f][0], a[f][1], a[f][2], a[f][3], ra);
            }

            uint32_t bh[8][2];
#pragma unroll
            for (int g = 0; g < 4; g++) {
                const uint32_t rb = base + TILE_B +
                    (uint32_t)(wn + g * 16 + (lane & 7) + ((lane >> 4) << 3)) * PITCH +
                    koff + (((lane >> 3) & 1) << 4);
                LDSM4(bh[2*g][0], bh[2*g][1], bh[2*g+1][0], bh[2*g+1][1], rb);
            }

#pragma unroll
            for (int f = 0; f < 4; f++)
#pragma unroll
                for (int g = 0; g < 8; g++)
                    MMA16816F(acc[f][g], a[f], bh[g]);
        }
    };

    // ---- 3-stage pipeline over 8 k64 chunks
    load_stage(0, 0);
    load_stage(1, 64);

#pragma unroll
    for (int c = 0; c < 8; c++) {
        if (c < 7) { CP_WAIT(1); } else { CP_WAIT(0); }
        __syncthreads();
        if (c + 2 < 8) load_stage((c + 2) % NSTAGE, (c + 2) * 64);
        compute_stage(c % NSTAGE);
    }

    // ---- fp16 epilogue: stage in smem (pitch 136), coalesced 16B stores
    const int qrow = lane >> 2;          // 0..7
    const int qcol = (lane & 3) * 2;     // 0,2,4,6
    __half* C = ga_.C;
    __syncthreads();                     // stage buffers dead; reuse smem
    __half* st = (__half*)smem;
#pragma unroll
    for (int f = 0; f < 4; f++)
#pragma unroll
        for (int g = 0; g < 8; g++) {
            const int r0 = wm + f * 16 + qrow;
            const int c0 = wn + g * 8 + qcol;
            *(__half2*)(st + r0 * EPI_PITCH + c0) =
                __floats2half2_rn(acc[f][g][0], acc[f][g][1]);
            *(__half2*)(st + (r0 + 8) * EPI_PITCH + c0) =
                __floats2half2_rn(acc[f][g][2], acc[f][g][3]);
        }
    __syncthreads();
#pragma unroll
    for (int i = 0; i < 16; i++) {
        const int idx = tid + 128 * i;       // 0..2047 (128 rows x 16 chunks)
        const int r = idx >> 4;
        const int c = idx & 15;
        *(uint4*)((char*)(C + (size_t)(bm0 + r) * 512 + bn0) + c * 16) =
            *(const uint4*)((const char*)(st + r * EPI_PITCH) + c * 16);
    }
}

// ---------------------------------------------------------------------------
// conv_all: ALL input conversion in one launch. 1-D grid, 256 threads.
//   blocks [0, 4096)     : guide transpose tiles (512 m x 8 k)
//   blocks [4096, 4352)  : low transpose tiles   (32 m x 8 k)
//   blocks [4352, 5376)  : weight round          (4 x 256)
// ---------------------------------------------------------------------------
__global__ __launch_bounds__(256)
void conv_all(const float* __restrict__ guide, const float* __restrict__ low,
              const float4* __restrict__ w0, const float4* __restrict__ w1,
              const float4* __restrict__ w2, const float4* __restrict__ w3,
              __half* __restrict__ Af, __half* __restrict__ Lf,
              __half* __restrict__ whi)
{
    const int b = blockIdx.x;
    const int tid = threadIdx.x;

    if (b < 4352) {
        const float* in;
        __half* outp;
        int M, mtile, ktile;
        if (b < 4096) { in = guide; outp = Af; M = NPOS; mtile = b & 511; ktile = b >> 9; }
        else { const int id = b - 4096; in = low; outp = Lf; M = LPOS; mtile = id & 31; ktile = id >> 5; }

        __shared__ float t[64][33];
        const int mb = mtile * 32, kb = ktile * 64;

#pragma unroll
        for (int q = 0; q < 2; q++) {
            const int fid = tid + 256 * q;       // 0..511
            const int kr  = fid >> 3;            // 0..63
            const int c4  = fid & 7;             // m-chunk of 4
            const float4 v = *(const float4*)(in + (size_t)(kb + kr) * M + mb + c4 * 4);
            t[kr][c4 * 4 + 0] = v.x;
            t[kr][c4 * 4 + 1] = v.y;
            t[kr][c4 * 4 + 2] = v.z;
            t[kr][c4 * 4 + 3] = v.w;
        }
        __syncthreads();

#pragma unroll
        for (int q = 0; q < 4; q++) {
            const int i  = tid + 256 * q;        // 0..1023
            const int m  = i >> 5;               // 0..31
            const int kh = i & 31;               // k-pair 0..31
            const __half2 h = __floats2half2_rn(t[2 * kh][m], t[2 * kh + 1][m]);
            *(__half2*)(outp + (size_t)(mb + m) * 512 + kb + 2 * kh) = h;
        }
    } else {
        const int id = b - 4352;                 // 0..1023
        const int z = id >> 8;
        const float4* src = (z == 0) ? w0 : (z == 1) ? w1 : (z == 2) ? w2 : w3;
        const int i = (id & 255) * 256 + tid;    // 0..65535
        const float4 v = src[i];

        const __half hx = __float2half(v.x), hy = __float2half(v.y);
        const __half hz = __float2half(v.z), hw = __float2half(v.w);

        const size_t o = (size_t)z * (DMODEL * DMODEL / 4) + i;
        ((ushort4*)whi)[o] = make_ushort4(__half_as_ushort(hx), __half_as_ushort(hy),
                                          __half_as_ushort(hz), __half_as_ushort(hw));
    }
}

// ---------------------------------------------------------------------------
// Windowed attention, 256 threads: tid = head*32 + half*16 + pos.
// K/V staged in smem as raw fp16; ALL data movement vectorized to 16B
// (uint4 LDG/LDS/STG; smem reads are 2-address broadcasts, conflict-free).
// Per-accumulator FMA order identical to the scalar version (bit-identical).
// One block per 4x4 guide tile. Writes fp16 msg.
// ---------------------------------------------------------------------------
__global__ __launch_bounds__(256)
void attn_kernel(const __half* __restrict__ Q, const __half* __restrict__ Km,
                 const __half* __restrict__ Vm, __half* __restrict__ msg)
{
    __shared__ __half Ks[9][512];
    __shared__ __half Vs[9][512];

    const int tx = blockIdx.x;
    const int ty = blockIdx.y;
    const int tid = threadIdx.x;

    for (int idx = tid; idx < 9 * 64; idx += 256) {
        const int k = idx >> 6;
        const int c = idx & 63;            // uint4 slot (8 halves)
        const int yy = min(max(ty - 1 + k / 3, 0), 31);
        const int xx = min(max(tx - 1 + k % 3, 0), 31);
        const int p  = yy * 32 + xx;
        ((uint4*)&Ks[k][0])[c] = ((const uint4*)(Km + (size_t)p * 512))[c];
        ((uint4*)&Vs[k][0])[c] = ((const uint4*)(Vm + (size_t)p * 512))[c];
    }
    __syncthreads();

    const int pos  = tid & 15;           // 0..15
    const int half = (tid >> 4) & 1;     // 0..1
    const int head = tid >> 5;           // 0..7
    const int n = (ty * 4 + (pos >> 2)) * 128 + tx * 4 + (pos & 3);
    const int coff = head * 64 + half * 32;   // this thread's 32 channels

    // preload Q: 32 halves = 4 x uint4
    uint4 qr[4];
    {
        const uint4* q4 = (const uint4*)(Q + (size_t)n * 512 + coff);
#pragma unroll
        for (int i = 0; i < 4; i++) qr[i] = q4[i];
    }

    float acc[9];
#pragma unroll
    for (int k = 0; k < 9; k++) acc[k] = 0.f;

#pragma unroll
    for (int e2 = 0; e2 < 4; e2++) {     // 8 halves (2 e-steps) per iteration
        const __half2* qh = (const __half2*)&qr[e2];
        const float2 qa0 = __half22float2(qh[0]);
        const float2 qb0 = __half22float2(qh[1]);
        const float2 qa1 = __half22float2(qh[2]);
        const float2 qb1 = __half22float2(qh[3]);
#pragma unroll
        for (int k = 0; k < 9; k++) {
            const uint4 kv = *(const uint4*)&Ks[k][coff + e2 * 8];
            const __half2* kh = (const __half2*)&kv;
            const float2 ka0 = __half22float2(kh[0]);
            const float2 kb0 = __half22float2(kh[1]);
            const float2 ka1 = __half22float2(kh[2]);
            const float2 kb1 = __half22float2(kh[3]);
            acc[k] += qa0.x * ka0.x + qa0.y * ka0.y + qb0.x * kb0.x + qb0.y * kb0.y;
            acc[k] += qa1.x * ka1.x + qa1.y * ka1.y + qb1.x * kb1.x + qb1.y * kb1.y;
        }
    }
    // combine the two halves (threads tid and tid^16 share a warp)
#pragma unroll
    for (int k = 0; k < 9; k++)
        acc[k] += __shfl_xor_sync(0xffffffffu, acc[k], 16);

    float mx = acc[0];
#pragma unroll
    for (int k = 1; k < 9; k++) mx = fmaxf(mx, acc[k]);
    float s = 0.f;
#pragma unroll
    for (int k = 0; k < 9; k++) { acc[k] = __expf(0.125f * (acc[k] - mx)); s += acc[k]; }
    const float inv = 1.f / s;
#pragma unroll
    for (int k = 0; k < 9; k++) acc[k] *= inv;

    __half* outp = msg + (size_t)n * 512 + coff;
#pragma unroll
    for (int e2 = 0; e2 < 4; e2++) {
        float4 o0 = make_float4(0.f, 0.f, 0.f, 0.f);
        float4 o1 = make_float4(0.f, 0.f, 0.f, 0.f);
#pragma unroll
        for (int k = 0; k < 9; k++) {
            const uint4 vv = *(const uint4*)&Vs[k][coff + e2 * 8];
            const __half2* vh = (const __half2*)&vv;
            const float2 va0 = __half22float2(vh[0]);
            const float2 vb0 = __half22float2(vh[1]);
            const float2 va1 = __half22float2(vh[2]);
            const float2 vb1 = __half22float2(vh[3]);
            o0.x += acc[k] * va0.x;
            o0.y += acc[k] * va0.y;
            o0.z += acc[k] * vb0.x;
            o0.w += acc[k] * vb0.y;
            o1.x += acc[k] * va1.x;
            o1.y += acc[k] * va1.y;
            o1.z += acc[k] * vb1.x;
            o1.w += acc[k] * vb1.y;
        }
        const __half2 h0 = __floats2half2_rn(o0.x, o0.y);
        const __half2 h1 = __floats2half2_rn(o0.z, o0.w);
        const __half2 h2 = __floats2half2_rn(o1.x, o1.y);
        const __half2 h3 = __floats2half2_rn(o1.z, o1.w);
        uint4 pk;
        pk.x = *(const uint32_t*)&h0;
        pk.y = *(const uint32_t*)&h1;
        pk.z = *(const uint32_t*)&h2;
        pk.w = *(const uint32_t*)&h3;
        *(uint4*)(outp + e2 * 8) = pk;
    }
}

// ---------------------------------------------------------------------------
// LayerNorm over d=512 per position (fp16 input, fp32 math) + transpose to
// channel-major fp32 output. Lane owns 16 CONSECUTIVE channels: 2 LDG.128,
// 4x float4 gamma/beta, 4 STS.128. Pitch 524 floats (gcd(131,32)=1) keeps
// the transposed read phase conflict-free. 32 positions per block; output
// warps write 32 consecutive positions (128B full-sector stores).
// ---------------------------------------------------------------------------
#define LN_PITCH 524
#define LN_SMEM  (32 * LN_PITCH * 4)     // 67072 B

__global__ __launch_bounds__(256)
void ln_kernel(const __half* __restrict__ X, const float* __restrict__ gamma,
               const float* __restrict__ beta, float* __restrict__ out)
{
    extern __shared__ float sm[];

    const int nb   = blockIdx.x * 32;
    const int warp = threadIdx.x >> 5;
    const int lane = threadIdx.x & 31;

    for (int r = warp; r < 32; r += 8) {
        const int n = nb + r;
        const uint4* row = (const uint4*)(X + (size_t)n * 512) + lane * 2;
        uint4 d0 = row[0];
        uint4 d1 = row[1];
        float v[16];
        {
            const __half2* h0 = (const __half2*)&d0;
            const __half2* h1 = (const __half2*)&d1;
#pragma unroll
            for (int j = 0; j < 4; j++) {
                const float2 a = __half22float2(h0[j]);
                const float2 bq = __half22float2(h1[j]);
                v[2 * j]     = a.x;  v[2 * j + 1] = a.y;
                v[8 + 2 * j] = bq.x; v[8 + 2 * j + 1] = bq.y;
            }
        }
        float s = 0.f;
#pragma unroll
        for (int j = 0; j < 16; j++) s += v[j];
#pragma unroll
        for (int o = 16; o > 0; o >>= 1) s += __shfl_xor_sync(0xffffffffu, s, o);
        const float mu = s * (1.f / 512.f);
        float q = 0.f;
#pragma unroll
        for (int j = 0; j < 16; j++) { float d = v[j] - mu; q += d * d; }
#pragma unroll
        for (int o = 16; o > 0; o >>= 1) q += __shfl_xor_sync(0xffffffffu, q, o);
        const float rstd = rsqrtf(q * (1.f / 512.f) + 1e-5f);

        // lane's channels: lane*16 .. lane*16+15 (consecutive)
#pragma unroll
        for (int j4 = 0; j4 < 4; j4++) {
            const float4 g = ((const float4*)gamma)[lane * 4 + j4];
            const float4 bb = ((const float4*)beta)[lane * 4 + j4];
            float4 o4;
            o4.x = (v[4 * j4 + 0] - mu) * rstd * g.x + bb.x;
            o4.y = (v[4 * j4 + 1] - mu) * rstd * g.y + bb.y;
            o4.z = (v[4 * j4 + 2] - mu) * rstd * g.z + bb.z;
            o4.w = (v[4 * j4 + 3] - mu) * rstd * g.w + bb.w;
            *(float4*)(sm + r * LN_PITCH + lane * 16 + j4 * 4) = o4;
        }
    }
    __syncthreads();

    const int i  = threadIdx.x & 31;     // position within the 32
    const int ob = threadIdx.x >> 5;     // 0..7
    for (int o = ob; o < 512; o += 8)
        out[(size_t)o * 16384 + nb + i] = sm[i * LN_PITCH + o];
}

// ---------------------------------------------------------------------------
extern "C" void kernel_launch(void* const* d_in, const int* in_sizes, int n_in,
                              void* d_out, int out_size)
{
    const float* low   = (const float*)d_in[0];
    const float* guide = (const float*)d_in[1];
    const float* Wq    = (const float*)d_in[2];
    const float* Wk    = (const float*)d_in[3];
    const float* Wv    = (const float*)d_in[4];
    const float* Wm    = (const float*)d_in[5];
    const float* gamma = (const float*)d_in[6];
    const float* beta  = (const float*)d_in[7];
    float* out = (float*)d_out;

    __half *Af, *Lf, *Whi, *Q, *K, *V;
    cudaGetSymbolAddress((void**)&Af,  g_Af);
    cudaGetSymbolAddress((void**)&Lf,  g_Lf);
    cudaGetSymbolAddress((void**)&Whi, g_Whi);
    cudaGetSymbolAddress((void**)&Q,   g_Q);
    cudaGetSymbolAddress((void**)&K,   g_K);
    cudaGetSymbolAddress((void**)&V,   g_V);

    const int W_ELEMS = DMODEL * DMODEL;              // 262144
    const int GEMM_SMEM = NSTAGE * STAGE_B;           // 110592

    cudaFuncSetAttribute(mma_gemm, cudaFuncAttributeMaxDynamicSharedMemorySize,
                         GEMM_SMEM);
    cudaFuncSetAttribute(ln_kernel, cudaFuncAttributeMaxDynamicSharedMemorySize,
                         LN_SMEM);

    // ALL conversions in one launch
    conv_all<<<5376, 256>>>(guide, low,
                            (const float4*)Wq, (const float4*)Wk,
                            (const float4*)Wv, (const float4*)Wm,
                            Af, Lf, Whi);

    // Q, K, V projections in ONE launch (1 MMA per k16), fp16 outputs
    {
        GemmArgs gq = { Af, Whi,               Q, 128 };
        GemmArgs gk = { Lf, Whi + 1 * W_ELEMS, K, 8 };
        GemmArgs gv = { Lf, Whi + 2 * W_ELEMS, V, 8 };
        mma_gemm<<<dim3(4, 128, 3), 128, GEMM_SMEM>>>(gq, gk, gv);
    }

    // Windowed attention -> fp16 msg directly into Af (guide no longer needed)
    attn_kernel<<<dim3(32, 32), 256>>>(Q, K, V, Af);

    // M2 = msg @ Wm^T, fp16 out into g_Q (Q is dead after attn)
    {
        GemmArgs gm = { Af, Whi + 3 * W_ELEMS, Q, 128 };
        mma_gemm<<<dim3(4, 128, 1), 128, GEMM_SMEM>>>(gm, gm, gm);
    }

    // LayerNorm (fp16 in, fp32 math, 32 pos/block) + channel-major output
    ln_kernel<<<512, 256, LN_SMEM>>>(Q, gamma, beta, out);
}